// round 11
// baseline (speedup 1.0000x reference)
#include <cuda_runtime.h>
#include <cuda_bf16.h>

// Problem constants
#define BSZ   2
#define SEQ   2048
#define HIDN  1024
#define HEADS 16
#define HD    64
#define NQB   32            // SEQ / 64
#define NQS   16            // SEQ / 128 (q-super-blocks)
#define MROWS (BSZ*SEQ)     // 4096

typedef __nv_bfloat16 bf16;

// Scratch (device globals)
__device__ bf16 g_xh[MROWS*HIDN], g_xl[MROWS*HIDN];
__device__ bf16 g_w8[8][HIDN*HIDN];       // Wq h,l  Wk h,l  Wv h,l  Wo h,l
__device__ bf16 g_qh[BSZ*HEADS*SEQ*HD], g_ql[BSZ*HEADS*SEQ*HD];
__device__ bf16 g_kh[BSZ*HEADS*SEQ*HD], g_kl[BSZ*HEADS*SEQ*HD];
__device__ bf16 g_vh[BSZ*HEADS*SEQ*HD], g_vl[BSZ*HEADS*SEQ*HD];
__device__ bf16 g_ah[MROWS*HIDN], g_al[MROWS*HIDN];   // attn out [B,S,HID]

// ===========================================================================
// helpers
// ===========================================================================
__device__ __forceinline__ unsigned smem_u32(const void* p) {
    unsigned a;
    asm("{ .reg .u64 t; cvta.to.shared.u64 t, %1; cvt.u32.u64 %0, t; }"
        : "=r"(a) : "l"(p));
    return a;
}
__device__ __forceinline__ void ldsm4(unsigned* r, unsigned addr) {
    asm volatile("ldmatrix.sync.aligned.m8n8.x4.shared.b16 {%0,%1,%2,%3}, [%4];"
                 : "=r"(r[0]), "=r"(r[1]), "=r"(r[2]), "=r"(r[3]) : "r"(addr));
}
__device__ __forceinline__ void ldsm4t(unsigned* r, unsigned addr) {
    asm volatile("ldmatrix.sync.aligned.m8n8.x4.trans.shared.b16 {%0,%1,%2,%3}, [%4];"
                 : "=r"(r[0]), "=r"(r[1]), "=r"(r[2]), "=r"(r[3]) : "r"(addr));
}
__device__ __forceinline__ void mma16816(float* c, const unsigned* a,
                                         const unsigned* b) {
    asm volatile(
        "mma.sync.aligned.m16n8k16.row.col.f32.bf16.bf16.f32 "
        "{%0,%1,%2,%3}, {%4,%5,%6,%7}, {%8,%9}, {%0,%1,%2,%3};"
        : "+f"(c[0]), "+f"(c[1]), "+f"(c[2]), "+f"(c[3])
        : "r"(a[0]), "r"(a[1]), "r"(a[2]), "r"(a[3]), "r"(b[0]), "r"(b[1]));
}
__device__ __forceinline__ unsigned pack_bf16(bf16 x, bf16 y) {
    return ((unsigned)__bfloat16_as_ushort(y) << 16) | __bfloat16_as_ushort(x);
}
#define CP_ASYNC16(dst, src) \
    asm volatile("cp.async.cg.shared.global [%0], [%1], 16;" :: "r"(dst), "l"(src))
#define CP_COMMIT() asm volatile("cp.async.commit_group;" ::: "memory")
#define CP_WAIT0()  asm volatile("cp.async.wait_group 0;" ::: "memory")
#define CP_WAIT1()  asm volatile("cp.async.wait_group 1;" ::: "memory")

// ===========================================================================
// split kernel: fp32 -> bf16 hi/lo
// ===========================================================================
__global__ void split_kernel(const float* __restrict__ src,
                             bf16* __restrict__ hi, bf16* __restrict__ lo,
                             int n4)
{
    const int base = (blockIdx.x * blockDim.x + threadIdx.x) * 2;
    if (base >= n4) return;
    float4 va = ((const float4*)src)[base];
    float4 vb = ((const float4*)src)[base + 1];
#pragma unroll
    for (int u = 0; u < 2; u++) {
        const float4 v = u ? vb : va;
        const int i = base + u;
        bf16 h0 = __float2bfloat16_rn(v.x);
        bf16 h1 = __float2bfloat16_rn(v.y);
        bf16 h2 = __float2bfloat16_rn(v.z);
        bf16 h3 = __float2bfloat16_rn(v.w);
        uint2 ho, lo2;
        ho.x = pack_bf16(h0, h1); ho.y = pack_bf16(h2, h3);
        lo2.x = pack_bf16(__float2bfloat16_rn(v.x - __bfloat162float(h0)),
                          __float2bfloat16_rn(v.y - __bfloat162float(h1)));
        lo2.y = pack_bf16(__float2bfloat16_rn(v.z - __bfloat162float(h2)),
                          __float2bfloat16_rn(v.w - __bfloat162float(h3)));
        ((uint2*)hi)[i] = ho;
        ((uint2*)lo)[i] = lo2;
    }
}

// ===========================================================================
// GEMM (unchanged from R10): BK=64, 3-stage cp.async, bf16 3-split.
// ===========================================================================
#define GST       72
#define GTILE_B   (128 * GST * 2)        // 18432 B per tile
#define GSTAGE_B  (4 * GTILE_B)          // 73728 B
#define GSM_BYTES (3 * GSTAGE_B)         // 221184 B
#define NCHUNK    (HIDN / 64)            // 16

__global__ __launch_bounds__(256)
void gemm_mma3(const bf16* __restrict__ Ah, const bf16* __restrict__ Al,
               const bf16* __restrict__ Wh, const bf16* __restrict__ Wl,
               const float* __restrict__ bias,
               float* __restrict__ Cf, bf16* __restrict__ Oh,
               bf16* __restrict__ Ol, float scl, int scatter)
{
    extern __shared__ char sm[];
    const int tid  = threadIdx.x;
    const int lane = tid & 31;
    const int wid  = tid >> 5;
    const int wm   = wid >> 2;           // 0..1
    const int wn   = wid & 3;            // 0..3
    const int bn = blockIdx.x, bm = blockIdx.y;

    const bf16* gsrc[4];
    gsrc[0] = Ah + (size_t)bm * 128 * HIDN;
    gsrc[1] = Al + (size_t)bm * 128 * HIDN;
    gsrc[2] = Wh + (size_t)bn * 128 * HIDN;
    gsrc[3] = Wl + (size_t)bn * 128 * HIDN;

    auto issue = [&](int c) {
        char* st = sm + (c % 3) * GSTAGE_B;
        const int kt = c * 64;
#pragma unroll
        for (int t4 = 0; t4 < 4; t4++) {
#pragma unroll
            for (int j = 0; j < 4; j++) {
                const int ch = tid + j * 256;
                const int row = ch >> 3, cc = ch & 7;
                unsigned dst = smem_u32(st + t4 * GTILE_B + (row * GST + cc * 8) * 2);
                const bf16* src = gsrc[t4] + (size_t)row * HIDN + kt + cc * 8;
                CP_ASYNC16(dst, src);
            }
        }
        CP_COMMIT();
    };

    issue(0);
    issue(1);

    float acc[4][4][4];
#pragma unroll
    for (int i = 0; i < 4; i++)
#pragma unroll
        for (int j = 0; j < 4; j++)
#pragma unroll
            for (int k = 0; k < 4; k++) acc[i][j][k] = 0.f;

    const int fr = lane & 15;
    const int fc = (lane >> 4) << 3;

    for (int c = 0; c < NCHUNK; c++) {
        CP_WAIT1();
        __syncthreads();
        if (c + 2 < NCHUNK) issue(c + 2);

        const unsigned sb = smem_u32(sm) + (c % 3) * GSTAGE_B;
        const unsigned uAh = sb, uAl = sb + GTILE_B;
        const unsigned uWh = sb + 2 * GTILE_B, uWl = sb + 3 * GTILE_B;

#pragma unroll
        for (int ks = 0; ks < 4; ks++) {
            const int kcol = ks * 16 + fc;
            unsigned ah[4][4], al[4][4], bh[4][2], bl[4][2];
#pragma unroll
            for (int mt = 0; mt < 4; mt++) {
                const unsigned off = ((wm * 64 + mt * 16 + fr) * GST + kcol) * 2;
                ldsm4(ah[mt], uAh + off);
                ldsm4(al[mt], uAl + off);
            }
#pragma unroll
            for (int ntp = 0; ntp < 2; ntp++) {
                const unsigned off = ((wn * 32 + ntp * 16 + fr) * GST + kcol) * 2;
                unsigned r[4];
                ldsm4(r, uWh + off);
                bh[2*ntp][0] = r[0]; bh[2*ntp+1][0] = r[1];
                bh[2*ntp][1] = r[2]; bh[2*ntp+1][1] = r[3];
                ldsm4(r, uWl + off);
                bl[2*ntp][0] = r[0]; bl[2*ntp+1][0] = r[1];
                bl[2*ntp][1] = r[2]; bl[2*ntp+1][1] = r[3];
            }
#pragma unroll
            for (int mt = 0; mt < 4; mt++)
#pragma unroll
                for (int nt = 0; nt < 4; nt++) {
                    mma16816(acc[mt][nt], ah[mt], bh[nt]);
                    mma16816(acc[mt][nt], ah[mt], bl[nt]);
                    mma16816(acc[mt][nt], al[mt], bh[nt]);
                }
        }
    }

    const int g = lane >> 2, t = lane & 3;
#pragma unroll
    for (int mt = 0; mt < 4; mt++) {
#pragma unroll
        for (int nt = 0; nt < 4; nt++) {
            const int n = bn * 128 + wn * 32 + nt * 8 + 2 * t;
            const float2 bi = *(const float2*)(bias + n);
            const int m0 = bm * 128 + wm * 64 + mt * 16 + g;
#pragma unroll
            for (int half = 0; half < 2; half++) {
                const int m = m0 + half * 8;
                float vx = (acc[mt][nt][half * 2 + 0] + bi.x) * scl;
                float vy = (acc[mt][nt][half * 2 + 1] + bi.y) * scl;
                if (!scatter) {
                    *(float2*)(Cf + (size_t)m * HIDN + n) = make_float2(vx, vy);
                } else {
                    const int b = m >> 11, s = m & 2047;
                    const int h = n >> 6,  d = n & 63;
                    const size_t idx =
                        (((size_t)(b * HEADS + h)) * SEQ + s) * HD + d;
                    bf16 h0 = __float2bfloat16_rn(vx);
                    bf16 h1 = __float2bfloat16_rn(vy);
                    *(unsigned*)(Oh + idx) = pack_bf16(h0, h1);
                    *(unsigned*)(Ol + idx) = pack_bf16(
                        __float2bfloat16_rn(vx - __bfloat162float(h0)),
                        __float2bfloat16_rn(vy - __bfloat162float(h1)));
                }
            }
        }
    }
}

// ===========================================================================
// Block-causal flash attention, BM=128 (two 64-blocks per CTA), 512 threads.
// 16 warps: wm = wid>>1 (8 x 16-row groups), wn = wid&1 (k-half of 32).
// kb = 0..2*qs fully visible; kb = 2*qs+1 only for lower 64 rows (warp-
// predicated, no elementwise mask). Register softmax, cp.async KV dbuf.
// ===========================================================================
#define AST       72
#define ATILE_B   (64 * AST * 2)          // 9216 B  (64-row KV tile)
#define QTILE_B   (128 * AST * 2)         // 18432 B (128-row Q tile)
#define AOFF_STAGE (2 * QTILE_B)          // 36864
#define AOFF_XM   (AOFF_STAGE + 2 * 4 * ATILE_B)   // 110592
#define ATTN_SMEM (AOFF_XM + 4096)        // 114688 B

__global__ __launch_bounds__(512, 1)
void attn_mma3(const bf16* __restrict__ gqh, const bf16* __restrict__ gql,
               const bf16* __restrict__ gkh, const bf16* __restrict__ gkl,
               const bf16* __restrict__ gvh, const bf16* __restrict__ gvl,
               bf16* __restrict__ goh, bf16* __restrict__ gol)
{
    extern __shared__ char sm[];
    const int qs = NQS - 1 - blockIdx.x;    // heavy supers first
    const int h = blockIdx.y, b = blockIdx.z;
    const int tid  = threadIdx.x;
    const int lane = tid & 31;
    const int wid  = tid >> 5;
    const int wm   = wid >> 1;              // 0..7 (16-row groups)
    const int wn   = wid & 1;               // 0..1 (k-half)
    const int fr = lane & 15, fc = (lane >> 4) << 3;
    const int g  = lane >> 2, t = lane & 3;
    const int vkr = ((lane >> 4) << 3) + (lane & 7);
    const int vnc = ((lane >> 3) & 1) << 3;

    const size_t hb = ((size_t)(b * HEADS + h)) * SEQ * HD;
    const bf16* src_k[4];
    src_k[0] = gkh + hb; src_k[1] = gkl + hb;
    src_k[2] = gvh + hb; src_k[3] = gvl + hb;

    auto issueKV = [&](int kb) {
        char* st = sm + AOFF_STAGE + (kb & 1) * 4 * ATILE_B;
        const size_t koff = (size_t)kb * 64 * HD;
        const int row = tid >> 3, cc = tid & 7;   // 512 threads = 64 rows x 8
#pragma unroll
        for (int t4 = 0; t4 < 4; t4++) {
            unsigned dst = smem_u32(st + t4 * ATILE_B + (row * AST + cc * 8) * 2);
            CP_ASYNC16(dst, src_k[t4] + koff + row * HD + cc * 8);
        }
        CP_COMMIT();
    };

    issueKV(0);

    // Q tiles: 128 rows x 64, hi+lo
    {
        const bf16* qh = gqh + hb + (size_t)qs * 128 * HD;
        const bf16* ql = gql + hb + (size_t)qs * 128 * HD;
#pragma unroll
        for (int j = 0; j < 2; j++) {
            const int ch = tid + j * 512;          // 0..1023
            const int row = ch >> 3, cc = ch & 7;
            *(uint4*)(sm + (row * AST + cc * 8) * 2) =
                *(const uint4*)(qh + row * HD + cc * 8);
            *(uint4*)(sm + QTILE_B + (row * AST + cc * 8) * 2) =
                *(const uint4*)(ql + row * HD + cc * 8);
        }
    }

    const unsigned uQh = smem_u32(sm), uQl = uQh + QTILE_B;

    float o_acc[8][4];
#pragma unroll
    for (int i = 0; i < 8; i++)
#pragma unroll
        for (int j = 0; j < 4; j++) o_acc[i][j] = 0.f;
    float m0r = -1e30f, m1r = -1e30f, l0r = 0.f, l1r = 0.f;

    const int niter = 2 * qs + 2;
    for (int kb = 0; kb < niter; kb++) {
        CP_WAIT0();
        __syncthreads();
        if (kb + 1 < niter) issueKV(kb + 1);

        // masked diagonal iteration: upper-half warps inactive
        const bool act = !(kb == niter - 1 && wm < 4);

        float* xm = (float*)(sm + AOFF_XM + (kb & 1) * 2048);
        float* xl = xm + 256;

        const unsigned us = smem_u32(sm) + AOFF_STAGE + (kb & 1) * 4 * ATILE_B;
        const unsigned uKh = us, uKl = us + ATILE_B;
        const unsigned uVh = us + 2 * ATILE_B, uVl = us + 3 * ATILE_B;

        float sfr[4][4];
        float pm0 = -1e30f, pm1 = -1e30f, ps0 = 0.f, ps1 = 0.f;

        if (act) {
#pragma unroll
            for (int i = 0; i < 4; i++)
#pragma unroll
                for (int j = 0; j < 4; j++) sfr[i][j] = 0.f;

#pragma unroll
            for (int ks = 0; ks < 4; ks++) {
                const int kcol = ks * 16 + fc;
                unsigned qa_h[4], qa_l[4];
                const unsigned offa = ((wm * 16 + fr) * AST + kcol) * 2;
                ldsm4(qa_h, uQh + offa);
                ldsm4(qa_l, uQl + offa);
#pragma unroll
                for (int ntp = 0; ntp < 2; ntp++) {
                    const unsigned offb = ((wn * 32 + ntp * 16 + fr) * AST + kcol) * 2;
                    unsigned rh[4], rl[4];
                    ldsm4(rh, uKh + offb);
                    ldsm4(rl, uKl + offb);
                    unsigned bh0[2] = {rh[0], rh[2]}, bh1[2] = {rh[1], rh[3]};
                    unsigned bl0[2] = {rl[0], rl[2]}, bl1[2] = {rl[1], rl[3]};
                    mma16816(sfr[2*ntp],   qa_h, bh0);
                    mma16816(sfr[2*ntp],   qa_h, bl0);
                    mma16816(sfr[2*ntp],   qa_l, bh0);
                    mma16816(sfr[2*ntp+1], qa_h, bh1);
                    mma16816(sfr[2*ntp+1], qa_h, bl1);
                    mma16816(sfr[2*ntp+1], qa_l, bh1);
                }
            }

            pm0 = sfr[0][0]; pm1 = sfr[0][2];
#pragma unroll
            for (int nt = 0; nt < 4; nt++) {
                pm0 = fmaxf(pm0, fmaxf(sfr[nt][0], sfr[nt][1]));
                pm1 = fmaxf(pm1, fmaxf(sfr[nt][2], sfr[nt][3]));
            }
            pm0 = fmaxf(pm0, __shfl_xor_sync(0xffffffffu, pm0, 1));
            pm0 = fmaxf(pm0, __shfl_xor_sync(0xffffffffu, pm0, 2));
            pm1 = fmaxf(pm1, __shfl_xor_sync(0xffffffffu, pm1, 1));
            pm1 = fmaxf(pm1, __shfl_xor_sync(0xffffffffu, pm1, 2));

#pragma unroll
            for (int nt = 0; nt < 4; nt++) {
                sfr[nt][0] = __expf(sfr[nt][0] - pm0);
                sfr[nt][1] = __expf(sfr[nt][1] - pm0);
                sfr[nt][2] = __expf(sfr[nt][2] - pm1);
                sfr[nt][3] = __expf(sfr[nt][3] - pm1);
                ps0 += sfr[nt][0] + sfr[nt][1];
                ps1 += sfr[nt][2] + sfr[nt][3];
            }
            ps0 += __shfl_xor_sync(0xffffffffu, ps0, 1);
            ps0 += __shfl_xor_sync(0xffffffffu, ps0, 2);
            ps1 += __shfl_xor_sync(0xffffffffu, ps1, 1);
            ps1 += __shfl_xor_sync(0xffffffffu, ps1, 2);
        }

        if (t == 0) {
            xm[wn * 128 + wm * 16 + g]     = pm0;
            xm[wn * 128 + wm * 16 + g + 8] = pm1;
            xl[wn * 128 + wm * 16 + g]     = ps0;
            xl[wn * 128 + wm * 16 + g + 8] = ps1;
        }
        __syncthreads();

        const int r0 = wm * 16 + g;
        const float ma0 = xm[r0],    mb0 = xm[128 + r0];
        const float la0 = xl[r0],    lb0 = xl[128 + r0];
        const float ma1 = xm[r0+8],  mb1 = xm[128 + r0 + 8];
        const float la1 = xl[r0+8],  lb1 = xl[128 + r0 + 8];
        const float mt0 = fmaxf(ma0, mb0), mt1 = fmaxf(ma1, mb1);
        const float lt0 = la0 * __expf(ma0 - mt0) + lb0 * __expf(mb0 - mt0);
        const float lt1 = la1 * __expf(ma1 - mt1) + lb1 * __expf(mb1 - mt1);

        const float mnew0 = fmaxf(m0r, mt0), mnew1 = fmaxf(m1r, mt1);
        const float corr0 = __expf(m0r - mnew0), corr1 = __expf(m1r - mnew1);
        l0r = l0r * corr0 + lt0 * __expf(mt0 - mnew0);
        l1r = l1r * corr1 + lt1 * __expf(mt1 - mnew1);
        m0r = mnew0; m1r = mnew1;

#pragma unroll
        for (int n8 = 0; n8 < 8; n8++) {
            o_acc[n8][0] *= corr0; o_acc[n8][1] *= corr0;
            o_acc[n8][2] *= corr1; o_acc[n8][3] *= corr1;
        }

        if (act) {
            const float pf0 = __expf(pm0 - m0r), pf1 = __expf(pm1 - m1r);
#pragma unroll
            for (int nt = 0; nt < 4; nt++) {
                sfr[nt][0] *= pf0; sfr[nt][1] *= pf0;
                sfr[nt][2] *= pf1; sfr[nt][3] *= pf1;
            }

            // P -> A fragments (bf16 hi/lo) in registers
            unsigned pa_h[2][4], pa_l[2][4];
#pragma unroll
            for (int ks2 = 0; ks2 < 2; ks2++) {
                const int ntA = 2 * ks2, ntB = 2 * ks2 + 1;
                const float p00 = sfr[ntA][0], p01 = sfr[ntA][1];
                const float p02 = sfr[ntA][2], p03 = sfr[ntA][3];
                const float p10 = sfr[ntB][0], p11 = sfr[ntB][1];
                const float p12 = sfr[ntB][2], p13 = sfr[ntB][3];
                const bf16 h00 = __float2bfloat16_rn(p00), h01 = __float2bfloat16_rn(p01);
                const bf16 h02 = __float2bfloat16_rn(p02), h03 = __float2bfloat16_rn(p03);
                const bf16 h10 = __float2bfloat16_rn(p10), h11 = __float2bfloat16_rn(p11);
                const bf16 h12 = __float2bfloat16_rn(p12), h13 = __float2bfloat16_rn(p13);
                pa_h[ks2][0] = pack_bf16(h00, h01);
                pa_h[ks2][1] = pack_bf16(h02, h03);
                pa_h[ks2][2] = pack_bf16(h10, h11);
                pa_h[ks2][3] = pack_bf16(h12, h13);
                pa_l[ks2][0] = pack_bf16(
                    __float2bfloat16_rn(p00 - __bfloat162float(h00)),
                    __float2bfloat16_rn(p01 - __bfloat162float(h01)));
                pa_l[ks2][1] = pack_bf16(
                    __float2bfloat16_rn(p02 - __bfloat162float(h02)),
                    __float2bfloat16_rn(p03 - __bfloat162float(h03)));
                pa_l[ks2][2] = pack_bf16(
                    __float2bfloat16_rn(p10 - __bfloat162float(h10)),
                    __float2bfloat16_rn(p11 - __bfloat162float(h11)));
                pa_l[ks2][3] = pack_bf16(
                    __float2bfloat16_rn(p12 - __bfloat162float(h12)),
                    __float2bfloat16_rn(p13 - __bfloat162float(h13)));
            }

            // O += P V (this warp's k-half)
#pragma unroll
            for (int ks2 = 0; ks2 < 2; ks2++) {
#pragma unroll
                for (int nc = 0; nc < 4; nc++) {
                    const unsigned offv =
                        ((wn * 32 + ks2 * 16 + vkr) * AST + nc * 16 + vnc) * 2;
                    unsigned rh[4], rl[4];
                    ldsm4t(rh, uVh + offv);
                    ldsm4t(rl, uVl + offv);
                    unsigned bh0[2] = {rh[0], rh[2]}, bh1[2] = {rh[1], rh[3]};
                    unsigned bl0[2] = {rl[0], rl[2]}, bl1[2] = {rl[1], rl[3]};
                    mma16816(o_acc[nc*2],   pa_h[ks2], bh0);
                    mma16816(o_acc[nc*2],   pa_h[ks2], bl0);
                    mma16816(o_acc[nc*2],   pa_l[ks2], bh0);
                    mma16816(o_acc[nc*2+1], pa_h[ks2], bh1);
                    mma16816(o_acc[nc*2+1], pa_h[ks2], bl1);
                    mma16816(o_acc[nc*2+1], pa_l[ks2], bh1);
                }
            }
        }
        // no bottom sync: next top sync orders buffer reuse
    }
    __syncthreads();

    // cross-warp O reduction (wn=1 -> SMEM; wn=0 adds + writes split output)
    float* red = (float*)(sm + AOFF_STAGE);     // [128][66] = 33792 B
    if (wn == 1) {
#pragma unroll
        for (int n8 = 0; n8 < 8; n8++) {
            const int col = n8 * 8 + 2 * t;
            red[(wm * 16 + g)     * 66 + col]     = o_acc[n8][0];
            red[(wm * 16 + g)     * 66 + col + 1] = o_acc[n8][1];
            red[(wm * 16 + g + 8) * 66 + col]     = o_acc[n8][2];
            red[(wm * 16 + g + 8) * 66 + col + 1] = o_acc[n8][3];
        }
    }
    __syncthreads();
    if (wn == 0) {
        const float inv0 = 1.f / l0r, inv1 = 1.f / l1r;
        const size_t obase = ((size_t)(b * SEQ + qs * 128)) * HIDN + h * HD;
#pragma unroll
        for (int n8 = 0; n8 < 8; n8++) {
            const int col = n8 * 8 + 2 * t;
            const float v0 = (o_acc[n8][0] + red[(wm*16+g)*66 + col])     * inv0;
            const float v1 = (o_acc[n8][1] + red[(wm*16+g)*66 + col + 1]) * inv0;
            const float v2 = (o_acc[n8][2] + red[(wm*16+g+8)*66 + col])     * inv1;
            const float v3 = (o_acc[n8][3] + red[(wm*16+g+8)*66 + col + 1]) * inv1;
            const bf16 h0 = __float2bfloat16_rn(v0), h1 = __float2bfloat16_rn(v1);
            const bf16 h2 = __float2bfloat16_rn(v2), h3 = __float2bfloat16_rn(v3);
            const size_t i0 = obase + (size_t)(wm * 16 + g) * HIDN + col;
            const size_t i1 = obase + (size_t)(wm * 16 + g + 8) * HIDN + col;
            *(unsigned*)(goh + i0) = pack_bf16(h0, h1);
            *(unsigned*)(gol + i0) = pack_bf16(
                __float2bfloat16_rn(v0 - __bfloat162float(h0)),
                __float2bfloat16_rn(v1 - __bfloat162float(h1)));
            *(unsigned*)(goh + i1) = pack_bf16(h2, h3);
            *(unsigned*)(gol + i1) = pack_bf16(
                __float2bfloat16_rn(v2 - __bfloat162float(h2)),
                __float2bfloat16_rn(v3 - __bfloat162float(h3)));
        }
    }
}

// ---------------------------------------------------------------------------
extern "C" void kernel_launch(void* const* d_in, const int* in_sizes, int n_in,
                              void* d_out, int out_size)
{
    const float* x  = (const float*)d_in[0];
    const float* Wq = (const float*)d_in[1];
    const float* bq = (const float*)d_in[2];
    const float* Wk = (const float*)d_in[3];
    const float* bk = (const float*)d_in[4];
    const float* Wv = (const float*)d_in[5];
    const float* bv = (const float*)d_in[6];
    const float* Wo = (const float*)d_in[7];
    const float* bo = (const float*)d_in[8];
    float* out = (float*)d_out;

    bf16 *xh, *xl, *w8, *qh, *ql, *kh, *kl, *vh, *vl, *ah, *al;
    cudaGetSymbolAddress((void**)&xh, g_xh);
    cudaGetSymbolAddress((void**)&xl, g_xl);
    cudaGetSymbolAddress((void**)&w8, g_w8);
    cudaGetSymbolAddress((void**)&qh, g_qh);
    cudaGetSymbolAddress((void**)&ql, g_ql);
    cudaGetSymbolAddress((void**)&kh, g_kh);
    cudaGetSymbolAddress((void**)&kl, g_kl);
    cudaGetSymbolAddress((void**)&vh, g_vh);
    cudaGetSymbolAddress((void**)&vl, g_vl);
    cudaGetSymbolAddress((void**)&ah, g_ah);
    cudaGetSymbolAddress((void**)&al, g_al);

    cudaFuncSetAttribute(gemm_mma3,
                         cudaFuncAttributeMaxDynamicSharedMemorySize, GSM_BYTES);
    cudaFuncSetAttribute(attn_mma3,
                         cudaFuncAttributeMaxDynamicSharedMemorySize, ATTN_SMEM);

    const int W2 = HIDN * HIDN;

    split_kernel<<<(MROWS*HIDN/8 + 255)/256, 256>>>(x, xh, xl, MROWS*HIDN/4);
    split_kernel<<<(W2/8 + 255)/256, 256>>>(Wq, w8 + 0*W2, w8 + 1*W2, W2/4);
    split_kernel<<<(W2/8 + 255)/256, 256>>>(Wk, w8 + 2*W2, w8 + 3*W2, W2/4);
    split_kernel<<<(W2/8 + 255)/256, 256>>>(Wv, w8 + 4*W2, w8 + 5*W2, W2/4);
    split_kernel<<<(W2/8 + 255)/256, 256>>>(Wo, w8 + 6*W2, w8 + 7*W2, W2/4);

    dim3 ggrid(HIDN / 128, MROWS / 128);

    gemm_mma3<<<ggrid, 256, GSM_BYTES>>>(xh, xl, w8 + 0*W2, w8 + 1*W2, bq,
                                         nullptr, qh, ql, 0.125f, 1);
    gemm_mma3<<<ggrid, 256, GSM_BYTES>>>(xh, xl, w8 + 2*W2, w8 + 3*W2, bk,
                                         nullptr, kh, kl, 1.0f, 1);
    gemm_mma3<<<ggrid, 256, GSM_BYTES>>>(xh, xl, w8 + 4*W2, w8 + 5*W2, bv,
                                         nullptr, vh, vl, 1.0f, 1);

    attn_mma3<<<dim3(NQS, HEADS, BSZ), 512, ATTN_SMEM>>>(qh, ql, kh, kl,
                                                         vh, vl, ah, al);

    gemm_mma3<<<ggrid, 256, GSM_BYTES>>>(ah, al, w8 + 6*W2, w8 + 7*W2, bo,
                                         out, nullptr, nullptr, 1.0f, 0);
}

// round 12
// speedup vs baseline: 1.0561x; 1.0561x over previous
#include <cuda_runtime.h>
#include <cuda_bf16.h>

// Problem constants
#define BSZ   2
#define SEQ   2048
#define HIDN  1024
#define HEADS 16
#define HD    64
#define NQB   32            // SEQ / 64
#define MROWS (BSZ*SEQ)     // 4096

typedef __nv_bfloat16 bf16;

// Scratch (device globals)
__device__ bf16 g_xh[MROWS*HIDN], g_xl[MROWS*HIDN];
__device__ bf16 g_w8[8][HIDN*HIDN];       // Wq h,l  Wk h,l  Wv h,l  Wo h,l
__device__ bf16 g_qh[BSZ*HEADS*SEQ*HD], g_ql[BSZ*HEADS*SEQ*HD];
__device__ bf16 g_kh[BSZ*HEADS*SEQ*HD], g_kl[BSZ*HEADS*SEQ*HD];
__device__ bf16 g_vh[BSZ*HEADS*SEQ*HD], g_vl[BSZ*HEADS*SEQ*HD];
__device__ bf16 g_ah[MROWS*HIDN], g_al[MROWS*HIDN];   // attn out [B,S,HID]
__device__ unsigned g_ctr[2];                          // tile counters

// ===========================================================================
// helpers
// ===========================================================================
__device__ __forceinline__ unsigned smem_u32(const void* p) {
    unsigned a;
    asm("{ .reg .u64 t; cvta.to.shared.u64 t, %1; cvt.u32.u64 %0, t; }"
        : "=r"(a) : "l"(p));
    return a;
}
__device__ __forceinline__ void ldsm4(unsigned* r, unsigned addr) {
    asm volatile("ldmatrix.sync.aligned.m8n8.x4.shared.b16 {%0,%1,%2,%3}, [%4];"
                 : "=r"(r[0]), "=r"(r[1]), "=r"(r[2]), "=r"(r[3]) : "r"(addr));
}
__device__ __forceinline__ void ldsm4t(unsigned* r, unsigned addr) {
    asm volatile("ldmatrix.sync.aligned.m8n8.x4.trans.shared.b16 {%0,%1,%2,%3}, [%4];"
                 : "=r"(r[0]), "=r"(r[1]), "=r"(r[2]), "=r"(r[3]) : "r"(addr));
}
__device__ __forceinline__ void mma16816(float* c, const unsigned* a,
                                         const unsigned* b) {
    asm volatile(
        "mma.sync.aligned.m16n8k16.row.col.f32.bf16.bf16.f32 "
        "{%0,%1,%2,%3}, {%4,%5,%6,%7}, {%8,%9}, {%0,%1,%2,%3};"
        : "+f"(c[0]), "+f"(c[1]), "+f"(c[2]), "+f"(c[3])
        : "r"(a[0]), "r"(a[1]), "r"(a[2]), "r"(a[3]), "r"(b[0]), "r"(b[1]));
}
__device__ __forceinline__ unsigned pack_bf16(bf16 x, bf16 y) {
    return ((unsigned)__bfloat16_as_ushort(y) << 16) | __bfloat16_as_ushort(x);
}
#define CP_ASYNC16(dst, src) \
    asm volatile("cp.async.cg.shared.global [%0], [%1], 16;" :: "r"(dst), "l"(src))
#define CP_COMMIT() asm volatile("cp.async.commit_group;" ::: "memory")
#define CP_WAIT0()  asm volatile("cp.async.wait_group 0;" ::: "memory")

// ===========================================================================
// counter reset (graph-capturable, deterministic)
// ===========================================================================
__global__ void reset_ctr_kernel() { g_ctr[0] = 0; g_ctr[1] = 0; }

// ===========================================================================
// split kernel: fp32 -> bf16 hi/lo
// ===========================================================================
__global__ void split_kernel(const float* __restrict__ src,
                             bf16* __restrict__ hi, bf16* __restrict__ lo,
                             int n4)
{
    const int base = (blockIdx.x * blockDim.x + threadIdx.x) * 2;
    if (base >= n4) return;
    float4 va = ((const float4*)src)[base];
    float4 vb = ((const float4*)src)[base + 1];
#pragma unroll
    for (int u = 0; u < 2; u++) {
        const float4 v = u ? vb : va;
        const int i = base + u;
        bf16 h0 = __float2bfloat16_rn(v.x);
        bf16 h1 = __float2bfloat16_rn(v.y);
        bf16 h2 = __float2bfloat16_rn(v.z);
        bf16 h3 = __float2bfloat16_rn(v.w);
        uint2 ho, lo2;
        ho.x = pack_bf16(h0, h1); ho.y = pack_bf16(h2, h3);
        lo2.x = pack_bf16(__float2bfloat16_rn(v.x - __bfloat162float(h0)),
                          __float2bfloat16_rn(v.y - __bfloat162float(h1)));
        lo2.y = pack_bf16(__float2bfloat16_rn(v.z - __bfloat162float(h2)),
                          __float2bfloat16_rn(v.w - __bfloat162float(h3)));
        ((uint2*)hi)[i] = ho;
        ((uint2*)lo)[i] = lo2;
    }
}

// ===========================================================================
// Persistent GEMM: tiles pulled from a global atomic counter.
// Tile t: matrix m = t>>8, tt = t&255, bm = tt>>3, bn = tt&7.
// C = A @ W^T + bias; BK=32, 2-stage cp.async, bf16 3-split MMA.
// Job.Cf != nullptr: fp32 row-major out; else bf16 hi/lo scatter to [B,H,S,D].
// ===========================================================================
struct Job {
    const bf16* Wh; const bf16* Wl;
    const float* bias;
    bf16* Oh; bf16* Ol;
    float* Cf;
    float scl;
};

#define GST       40
#define GTILE_B   (128 * GST * 2)        // 10240 B per component tile
#define GSTAGE_B  (4 * GTILE_B)          // 40960 B
#define GSM_BYTES (2 * GSTAGE_B + 128)   // 82048 B
#define NCH2      (HIDN / 32)            // 32 chunks

__global__ __launch_bounds__(256, 2)
void gemm_pers(unsigned* ctr, int ntot,
               const bf16* __restrict__ Ah, const bf16* __restrict__ Al,
               Job j0, Job j1, Job j2)
{
    extern __shared__ char sm[];
    volatile int* slot = (volatile int*)(sm + 2 * GSTAGE_B);
    const int tid  = threadIdx.x;
    const int lane = tid & 31;
    const int wid  = tid >> 5;
    const int wm   = wid >> 2;           // 0..1
    const int wn   = wid & 3;            // 0..3

    const bf16* gsrc[4];

    auto setsrc = [&](int tile) {
        const int m  = tile >> 8;
        const int tt = tile & 255;
        const int bm = tt >> 3, bn = tt & 7;
        const Job& jb = (m == 0) ? j0 : (m == 1 ? j1 : j2);
        gsrc[0] = Ah + (size_t)bm * 128 * HIDN;
        gsrc[1] = Al + (size_t)bm * 128 * HIDN;
        gsrc[2] = jb.Wh + (size_t)bn * 128 * HIDN;
        gsrc[3] = jb.Wl + (size_t)bn * 128 * HIDN;
    };

    auto issue = [&](int kt, int buf) {
        char* st = sm + buf * GSTAGE_B;
#pragma unroll
        for (int t4 = 0; t4 < 4; t4++) {
#pragma unroll
            for (int j = 0; j < 2; j++) {
                const int ch = tid + j * 256;       // 0..511
                const int row = ch >> 2, cc = ch & 3;
                unsigned dst = smem_u32(st + t4 * GTILE_B + (row * GST + cc * 8) * 2);
                const bf16* src = gsrc[t4] + (size_t)row * HIDN + kt + cc * 8;
                CP_ASYNC16(dst, src);
            }
        }
        CP_COMMIT();
    };

    // acquire first tile
    if (tid == 0) *slot = (int)atomicAdd(ctr, 1u);
    __syncthreads();
    int t = *slot;
    if (t >= ntot) return;
    setsrc(t);
    issue(0, 0);

    const int fr = lane & 15;
    const int fc = (lane >> 4) << 3;
    const int g = lane >> 2, tq = lane & 3;

    while (true) {
        float acc[4][4][4];
#pragma unroll
        for (int i = 0; i < 4; i++)
#pragma unroll
            for (int j = 0; j < 4; j++)
#pragma unroll
                for (int k = 0; k < 4; k++) acc[i][j][k] = 0.f;

        int tn = ntot;
        for (int c = 0; c < NCH2; c++) {
            CP_WAIT0();
            __syncthreads();
            if (c == NCH2 - 2 && tid == 0) *slot = (int)atomicAdd(ctr, 1u);
            if (c < NCH2 - 1) {
                issue((c + 1) * 32, (c + 1) & 1);
            } else {
                tn = *slot;                 // visible: written last iter, synced above
                if (tn < ntot) { setsrc(tn); issue(0, 0); }
            }

            const unsigned sb = smem_u32(sm) + (c & 1) * GSTAGE_B;
            const unsigned uAh = sb, uAl = sb + GTILE_B;
            const unsigned uWh = sb + 2 * GTILE_B, uWl = sb + 3 * GTILE_B;

#pragma unroll
            for (int ks = 0; ks < 2; ks++) {
                const int kcol = ks * 16 + fc;
                unsigned ah[4][4], al[4][4], bh[4][2], bl[4][2];
#pragma unroll
                for (int mt = 0; mt < 4; mt++) {
                    const unsigned off = ((wm * 64 + mt * 16 + fr) * GST + kcol) * 2;
                    ldsm4(ah[mt], uAh + off);
                    ldsm4(al[mt], uAl + off);
                }
#pragma unroll
                for (int ntp = 0; ntp < 2; ntp++) {
                    const unsigned off = ((wn * 32 + ntp * 16 + fr) * GST + kcol) * 2;
                    unsigned r[4];
                    ldsm4(r, uWh + off);
                    bh[2*ntp][0] = r[0]; bh[2*ntp+1][0] = r[1];
                    bh[2*ntp][1] = r[2]; bh[2*ntp+1][1] = r[3];
                    ldsm4(r, uWl + off);
                    bl[2*ntp][0] = r[0]; bl[2*ntp+1][0] = r[1];
                    bl[2*ntp][1] = r[2]; bl[2*ntp+1][1] = r[3];
                }
#pragma unroll
                for (int mt = 0; mt < 4; mt++)
#pragma unroll
                    for (int nt = 0; nt < 4; nt++) {
                        mma16816(acc[mt][nt], ah[mt], bh[nt]);
                        mma16816(acc[mt][nt], ah[mt], bl[nt]);
                        mma16816(acc[mt][nt], al[mt], bh[nt]);
                    }
            }
        }

        // epilogue for tile t
        {
            const int m  = t >> 8;
            const int tt = t & 255;
            const int bm = tt >> 3, bn = tt & 7;
            const Job& jb = (m == 0) ? j0 : (m == 1 ? j1 : j2);
#pragma unroll
            for (int mt = 0; mt < 4; mt++) {
#pragma unroll
                for (int nt = 0; nt < 4; nt++) {
                    const int n = bn * 128 + wn * 32 + nt * 8 + 2 * tq;
                    const float2 bi = *(const float2*)(jb.bias + n);
                    const int m0 = bm * 128 + wm * 64 + mt * 16 + g;
#pragma unroll
                    for (int half = 0; half < 2; half++) {
                        const int mr = m0 + half * 8;
                        float vx = (acc[mt][nt][half * 2 + 0] + bi.x) * jb.scl;
                        float vy = (acc[mt][nt][half * 2 + 1] + bi.y) * jb.scl;
                        if (jb.Cf) {
                            *(float2*)(jb.Cf + (size_t)mr * HIDN + n) =
                                make_float2(vx, vy);
                        } else {
                            const int b = mr >> 11, s = mr & 2047;
                            const int hh = n >> 6, d = n & 63;
                            const size_t idx =
                                (((size_t)(b * HEADS + hh)) * SEQ + s) * HD + d;
                            bf16 h0 = __float2bfloat16_rn(vx);
                            bf16 h1 = __float2bfloat16_rn(vy);
                            *(unsigned*)(jb.Oh + idx) = pack_bf16(h0, h1);
                            *(unsigned*)(jb.Ol + idx) = pack_bf16(
                                __float2bfloat16_rn(vx - __bfloat162float(h0)),
                                __float2bfloat16_rn(vy - __bfloat162float(h1)));
                        }
                    }
                }
            }
        }

        if (tn >= ntot) return;
        t = tn;
    }
}

// ===========================================================================
// Block-causal flash attention (R10 version — best known): pre-split inputs,
// cp.async KV double-buffer, register softmax, dbuf m/l exchange.
// ===========================================================================
#define AST     72
#define ATILE_B (64 * AST * 2)            // 9216 B
#define AOFF_STAGE 18432
#define AOFF_XM  (AOFF_STAGE + 2 * 4 * ATILE_B)   // 92160
#define ATTN_SMEM (AOFF_XM + 2048)        // 94208 B

__global__ __launch_bounds__(256, 2)
void attn_mma2(const bf16* __restrict__ gqh, const bf16* __restrict__ gql,
               const bf16* __restrict__ gkh, const bf16* __restrict__ gkl,
               const bf16* __restrict__ gvh, const bf16* __restrict__ gvl,
               bf16* __restrict__ goh, bf16* __restrict__ gol)
{
    extern __shared__ char sm[];
    const int qb = NQB - 1 - blockIdx.x;
    const int h = blockIdx.y, b = blockIdx.z;
    const int tid  = threadIdx.x;
    const int lane = tid & 31;
    const int wid  = tid >> 5;
    const int wm   = wid >> 1;
    const int wn   = wid & 1;
    const int fr = lane & 15, fc = (lane >> 4) << 3;
    const int g  = lane >> 2, t = lane & 3;
    const int vkr = ((lane >> 4) << 3) + (lane & 7);
    const int vnc = ((lane >> 3) & 1) << 3;

    const size_t hb = ((size_t)(b * HEADS + h)) * SEQ * HD;
    const bf16* src_k[4];
    src_k[0] = gkh + hb; src_k[1] = gkl + hb;
    src_k[2] = gvh + hb; src_k[3] = gvl + hb;

    auto issueKV = [&](int kb) {
        char* st = sm + AOFF_STAGE + (kb & 1) * 4 * ATILE_B;
        const size_t koff = (size_t)kb * 64 * HD;
#pragma unroll
        for (int t4 = 0; t4 < 4; t4++) {
#pragma unroll
            for (int j = 0; j < 2; j++) {
                const int ch = tid + j * 256;
                const int row = ch >> 3, cc = ch & 7;
                unsigned dst = smem_u32(st + t4 * ATILE_B + (row * AST + cc * 8) * 2);
                const bf16* src = src_k[t4] + koff + row * HD + cc * 8;
                CP_ASYNC16(dst, src);
            }
        }
        CP_COMMIT();
    };

    issueKV(0);

    {
        const bf16* qh = gqh + hb + (size_t)qb * 64 * HD;
        const bf16* ql = gql + hb + (size_t)qb * 64 * HD;
#pragma unroll
        for (int j = 0; j < 2; j++) {
            const int ch = tid + j * 256;
            const int row = ch >> 3, cc = ch & 7;
            *(uint4*)(sm + (row * AST + cc * 8) * 2) =
                *(const uint4*)(qh + row * HD + cc * 8);
            *(uint4*)(sm + ATILE_B + (row * AST + cc * 8) * 2) =
                *(const uint4*)(ql + row * HD + cc * 8);
        }
    }

    const unsigned uQh = smem_u32(sm), uQl = uQh + ATILE_B;

    float o_acc[8][4];
#pragma unroll
    for (int i = 0; i < 8; i++)
#pragma unroll
        for (int j = 0; j < 4; j++) o_acc[i][j] = 0.f;
    float m0r = -1e30f, m1r = -1e30f, l0r = 0.f, l1r = 0.f;

    for (int kb = 0; kb <= qb; kb++) {
        CP_WAIT0();
        __syncthreads();
        if (kb + 1 <= qb) issueKV(kb + 1);

        float* xm = (float*)(sm + AOFF_XM + (kb & 1) * 512);
        float* xl = (float*)(sm + AOFF_XM + 1024 + (kb & 1) * 512);

        const unsigned us = smem_u32(sm) + AOFF_STAGE + (kb & 1) * 4 * ATILE_B;
        const unsigned uKh = us, uKl = us + ATILE_B;
        const unsigned uVh = us + 2 * ATILE_B, uVl = us + 3 * ATILE_B;

        float sfr[4][4];
#pragma unroll
        for (int i = 0; i < 4; i++)
#pragma unroll
            for (int j = 0; j < 4; j++) sfr[i][j] = 0.f;

#pragma unroll
        for (int ks = 0; ks < 4; ks++) {
            const int kcol = ks * 16 + fc;
            unsigned qa_h[4], qa_l[4];
            const unsigned offa = ((wm * 16 + fr) * AST + kcol) * 2;
            ldsm4(qa_h, uQh + offa);
            ldsm4(qa_l, uQl + offa);
#pragma unroll
            for (int ntp = 0; ntp < 2; ntp++) {
                const unsigned offb = ((wn * 32 + ntp * 16 + fr) * AST + kcol) * 2;
                unsigned rh[4], rl[4];
                ldsm4(rh, uKh + offb);
                ldsm4(rl, uKl + offb);
                unsigned bh0[2] = {rh[0], rh[2]}, bh1[2] = {rh[1], rh[3]};
                unsigned bl0[2] = {rl[0], rl[2]}, bl1[2] = {rl[1], rl[3]};
                mma16816(sfr[2*ntp],   qa_h, bh0);
                mma16816(sfr[2*ntp],   qa_h, bl0);
                mma16816(sfr[2*ntp],   qa_l, bh0);
                mma16816(sfr[2*ntp+1], qa_h, bh1);
                mma16816(sfr[2*ntp+1], qa_h, bl1);
                mma16816(sfr[2*ntp+1], qa_l, bh1);
            }
        }

        // register softmax
        float pm0 = sfr[0][0], pm1 = sfr[0][2];
#pragma unroll
        for (int nt = 0; nt < 4; nt++) {
            pm0 = fmaxf(pm0, fmaxf(sfr[nt][0], sfr[nt][1]));
            pm1 = fmaxf(pm1, fmaxf(sfr[nt][2], sfr[nt][3]));
        }
        pm0 = fmaxf(pm0, __shfl_xor_sync(0xffffffffu, pm0, 1));
        pm0 = fmaxf(pm0, __shfl_xor_sync(0xffffffffu, pm0, 2));
        pm1 = fmaxf(pm1, __shfl_xor_sync(0xffffffffu, pm1, 1));
        pm1 = fmaxf(pm1, __shfl_xor_sync(0xffffffffu, pm1, 2));

        float ps0 = 0.f, ps1 = 0.f;
#pragma unroll
        for (int nt = 0; nt < 4; nt++) {
            sfr[nt][0] = __expf(sfr[nt][0] - pm0);
            sfr[nt][1] = __expf(sfr[nt][1] - pm0);
            sfr[nt][2] = __expf(sfr[nt][2] - pm1);
            sfr[nt][3] = __expf(sfr[nt][3] - pm1);
            ps0 += sfr[nt][0] + sfr[nt][1];
            ps1 += sfr[nt][2] + sfr[nt][3];
        }
        ps0 += __shfl_xor_sync(0xffffffffu, ps0, 1);
        ps0 += __shfl_xor_sync(0xffffffffu, ps0, 2);
        ps1 += __shfl_xor_sync(0xffffffffu, ps1, 1);
        ps1 += __shfl_xor_sync(0xffffffffu, ps1, 2);

        if (t == 0) {
            xm[wn * 64 + wm * 16 + g]     = pm0;
            xm[wn * 64 + wm * 16 + g + 8] = pm1;
            xl[wn * 64 + wm * 16 + g]     = ps0;
            xl[wn * 64 + wm * 16 + g + 8] = ps1;
        }
        __syncthreads();

        const int r0 = wm * 16 + g;
        const float ma0 = xm[r0],    mb0 = xm[64 + r0];
        const float la0 = xl[r0],    lb0 = xl[64 + r0];
        const float ma1 = xm[r0+8],  mb1 = xm[64 + r0 + 8];
        const float la1 = xl[r0+8],  lb1 = xl[64 + r0 + 8];
        const float mt0 = fmaxf(ma0, mb0), mt1 = fmaxf(ma1, mb1);
        const float lt0 = la0 * __expf(ma0 - mt0) + lb0 * __expf(mb0 - mt0);
        const float lt1 = la1 * __expf(ma1 - mt1) + lb1 * __expf(mb1 - mt1);

        const float mnew0 = fmaxf(m0r, mt0), mnew1 = fmaxf(m1r, mt1);
        const float corr0 = __expf(m0r - mnew0), corr1 = __expf(m1r - mnew1);
        l0r = l0r * corr0 + lt0 * __expf(mt0 - mnew0);
        l1r = l1r * corr1 + lt1 * __expf(mt1 - mnew1);
        m0r = mnew0; m1r = mnew1;

        const float pf0 = __expf(pm0 - mnew0), pf1 = __expf(pm1 - mnew1);
#pragma unroll
        for (int nt = 0; nt < 4; nt++) {
            sfr[nt][0] *= pf0; sfr[nt][1] *= pf0;
            sfr[nt][2] *= pf1; sfr[nt][3] *= pf1;
        }
#pragma unroll
        for (int n8 = 0; n8 < 8; n8++) {
            o_acc[n8][0] *= corr0; o_acc[n8][1] *= corr0;
            o_acc[n8][2] *= corr1; o_acc[n8][3] *= corr1;
        }

        // P -> A fragments (bf16 hi/lo) in registers
        unsigned pa_h[2][4], pa_l[2][4];
#pragma unroll
        for (int ks2 = 0; ks2 < 2; ks2++) {
            const int ntA = 2 * ks2, ntB = 2 * ks2 + 1;
            const float p00 = sfr[ntA][0], p01 = sfr[ntA][1];
            const float p02 = sfr[ntA][2], p03 = sfr[ntA][3];
            const float p10 = sfr[ntB][0], p11 = sfr[ntB][1];
            const float p12 = sfr[ntB][2], p13 = sfr[ntB][3];
            const bf16 h00 = __float2bfloat16_rn(p00), h01 = __float2bfloat16_rn(p01);
            const bf16 h02 = __float2bfloat16_rn(p02), h03 = __float2bfloat16_rn(p03);
            const bf16 h10 = __float2bfloat16_rn(p10), h11 = __float2bfloat16_rn(p11);
            const bf16 h12 = __float2bfloat16_rn(p12), h13 = __float2bfloat16_rn(p13);
            pa_h[ks2][0] = pack_bf16(h00, h01);
            pa_h[ks2][1] = pack_bf16(h02, h03);
            pa_h[ks2][2] = pack_bf16(h10, h11);
            pa_h[ks2][3] = pack_bf16(h12, h13);
            pa_l[ks2][0] = pack_bf16(
                __float2bfloat16_rn(p00 - __bfloat162float(h00)),
                __float2bfloat16_rn(p01 - __bfloat162float(h01)));
            pa_l[ks2][1] = pack_bf16(
                __float2bfloat16_rn(p02 - __bfloat162float(h02)),
                __float2bfloat16_rn(p03 - __bfloat162float(h03)));
            pa_l[ks2][2] = pack_bf16(
                __float2bfloat16_rn(p10 - __bfloat162float(h10)),
                __float2bfloat16_rn(p11 - __bfloat162float(h11)));
            pa_l[ks2][3] = pack_bf16(
                __float2bfloat16_rn(p12 - __bfloat162float(h12)),
                __float2bfloat16_rn(p13 - __bfloat162float(h13)));
        }

        // O += P V (this warp's k-half)
#pragma unroll
        for (int ks2 = 0; ks2 < 2; ks2++) {
#pragma unroll
            for (int nc = 0; nc < 4; nc++) {
                const unsigned offv =
                    ((wn * 32 + ks2 * 16 + vkr) * AST + nc * 16 + vnc) * 2;
                unsigned rh[4], rl[4];
                ldsm4t(rh, uVh + offv);
                ldsm4t(rl, uVl + offv);
                unsigned bh0[2] = {rh[0], rh[2]}, bh1[2] = {rh[1], rh[3]};
                unsigned bl0[2] = {rl[0], rl[2]}, bl1[2] = {rl[1], rl[3]};
                mma16816(o_acc[nc*2],   pa_h[ks2], bh0);
                mma16816(o_acc[nc*2],   pa_h[ks2], bl0);
                mma16816(o_acc[nc*2],   pa_l[ks2], bh0);
                mma16816(o_acc[nc*2+1], pa_h[ks2], bh1);
                mma16816(o_acc[nc*2+1], pa_h[ks2], bl1);
                mma16816(o_acc[nc*2+1], pa_l[ks2], bh1);
            }
        }
        // no bottom sync: next top sync orders buffer reuse
    }
    __syncthreads();

    // cross-warp O reduction + split output
    float* red = (float*)(sm + AOFF_STAGE);     // [64][66]
    if (wn == 1) {
#pragma unroll
        for (int n8 = 0; n8 < 8; n8++) {
            const int col = n8 * 8 + 2 * t;
            red[(wm * 16 + g)     * 66 + col]     = o_acc[n8][0];
            red[(wm * 16 + g)     * 66 + col + 1] = o_acc[n8][1];
            red[(wm * 16 + g + 8) * 66 + col]     = o_acc[n8][2];
            red[(wm * 16 + g + 8) * 66 + col + 1] = o_acc[n8][3];
        }
    }
    __syncthreads();
    if (wn == 0) {
        const float inv0 = 1.f / l0r, inv1 = 1.f / l1r;
        const size_t obase = ((size_t)(b * SEQ + qb * 64)) * HIDN + h * HD;
#pragma unroll
        for (int n8 = 0; n8 < 8; n8++) {
            const int col = n8 * 8 + 2 * t;
            const float v0 = (o_acc[n8][0] + red[(wm*16+g)*66 + col])     * inv0;
            const float v1 = (o_acc[n8][1] + red[(wm*16+g)*66 + col + 1]) * inv0;
            const float v2 = (o_acc[n8][2] + red[(wm*16+g+8)*66 + col])     * inv1;
            const float v3 = (o_acc[n8][3] + red[(wm*16+g+8)*66 + col + 1]) * inv1;
            const bf16 h0 = __float2bfloat16_rn(v0), h1 = __float2bfloat16_rn(v1);
            const bf16 h2 = __float2bfloat16_rn(v2), h3 = __float2bfloat16_rn(v3);
            const size_t i0 = obase + (size_t)(wm * 16 + g) * HIDN + col;
            const size_t i1 = obase + (size_t)(wm * 16 + g + 8) * HIDN + col;
            *(unsigned*)(goh + i0) = pack_bf16(h0, h1);
            *(unsigned*)(gol + i0) = pack_bf16(
                __float2bfloat16_rn(v0 - __bfloat162float(h0)),
                __float2bfloat16_rn(v1 - __bfloat162float(h1)));
            *(unsigned*)(goh + i1) = pack_bf16(h2, h3);
            *(unsigned*)(gol + i1) = pack_bf16(
                __float2bfloat16_rn(v2 - __bfloat162float(h2)),
                __float2bfloat16_rn(v3 - __bfloat162float(h3)));
        }
    }
}

// ---------------------------------------------------------------------------
extern "C" void kernel_launch(void* const* d_in, const int* in_sizes, int n_in,
                              void* d_out, int out_size)
{
    const float* x  = (const float*)d_in[0];
    const float* Wq = (const float*)d_in[1];
    const float* bq = (const float*)d_in[2];
    const float* Wk = (const float*)d_in[3];
    const float* bk = (const float*)d_in[4];
    const float* Wv = (const float*)d_in[5];
    const float* bv = (const float*)d_in[6];
    const float* Wo = (const float*)d_in[7];
    const float* bo = (const float*)d_in[8];
    float* out = (float*)d_out;

    bf16 *xh, *xl, *w8, *qh, *ql, *kh, *kl, *vh, *vl, *ah, *al;
    unsigned* ctr;
    cudaGetSymbolAddress((void**)&xh, g_xh);
    cudaGetSymbolAddress((void**)&xl, g_xl);
    cudaGetSymbolAddress((void**)&w8, g_w8);
    cudaGetSymbolAddress((void**)&qh, g_qh);
    cudaGetSymbolAddress((void**)&ql, g_ql);
    cudaGetSymbolAddress((void**)&kh, g_kh);
    cudaGetSymbolAddress((void**)&kl, g_kl);
    cudaGetSymbolAddress((void**)&vh, g_vh);
    cudaGetSymbolAddress((void**)&vl, g_vl);
    cudaGetSymbolAddress((void**)&ah, g_ah);
    cudaGetSymbolAddress((void**)&al, g_al);
    cudaGetSymbolAddress((void**)&ctr, g_ctr);

    cudaFuncSetAttribute(gemm_pers,
                         cudaFuncAttributeMaxDynamicSharedMemorySize, GSM_BYTES);
    cudaFuncSetAttribute(attn_mma2,
                         cudaFuncAttributeMaxDynamicSharedMemorySize, ATTN_SMEM);

    const int W2 = HIDN * HIDN;

    reset_ctr_kernel<<<1, 1>>>();
    split_kernel<<<(MROWS*HIDN/8 + 255)/256, 256>>>(x, xh, xl, MROWS*HIDN/4);
    split_kernel<<<(W2/8 + 255)/256, 256>>>(Wq, w8 + 0*W2, w8 + 1*W2, W2/4);
    split_kernel<<<(W2/8 + 255)/256, 256>>>(Wk, w8 + 2*W2, w8 + 3*W2, W2/4);
    split_kernel<<<(W2/8 + 255)/256, 256>>>(Wv, w8 + 4*W2, w8 + 5*W2, W2/4);
    split_kernel<<<(W2/8 + 255)/256, 256>>>(Wo, w8 + 6*W2, w8 + 7*W2, W2/4);

    Job jq = { w8 + 0*W2, w8 + 1*W2, bq, qh, ql, nullptr, 0.125f };
    Job jk = { w8 + 2*W2, w8 + 3*W2, bk, kh, kl, nullptr, 1.0f };
    Job jv = { w8 + 4*W2, w8 + 5*W2, bv, vh, vl, nullptr, 1.0f };
    Job jo = { w8 + 6*W2, w8 + 7*W2, bo, nullptr, nullptr, out, 1.0f };

    // Fused QKV: 768 tiles, dynamic stealing over 296 persistent CTAs
    gemm_pers<<<296, 256, GSM_BYTES>>>(ctr + 0, 768, xh, xl, jq, jk, jv);

    attn_mma2<<<dim3(NQB, HEADS, BSZ), 256, ATTN_SMEM>>>(qh, ql, kh, kl,
                                                         vh, vl, ah, al);

    // O projection: 256 tiles
    gemm_pers<<<296, 256, GSM_BYTES>>>(ctr + 1, 256, ah, al, jo, jo, jo);
}

// round 13
// speedup vs baseline: 1.0783x; 1.0210x over previous
#include <cuda_runtime.h>
#include <cuda_bf16.h>

// Problem constants
#define BSZ   2
#define SEQ   2048
#define HIDN  1024
#define HEADS 16
#define HD    64
#define NQB   32            // SEQ / 64
#define MROWS (BSZ*SEQ)     // 4096

typedef __nv_bfloat16 bf16;

// Scratch (device globals)
__device__ bf16 g_xh[MROWS*HIDN], g_xl[MROWS*HIDN];
__device__ bf16 g_w8[8][HIDN*HIDN];       // Wq h,l  Wk h,l  Wv h,l  Wo h,l
__device__ bf16 g_qh[BSZ*HEADS*SEQ*HD], g_ql[BSZ*HEADS*SEQ*HD];
__device__ bf16 g_kh[BSZ*HEADS*SEQ*HD], g_kl[BSZ*HEADS*SEQ*HD];
__device__ bf16 g_vh[BSZ*HEADS*SEQ*HD], g_vl[BSZ*HEADS*SEQ*HD];
__device__ bf16 g_ah[MROWS*HIDN], g_al[MROWS*HIDN];   // attn out [B,S,HID]
__device__ unsigned g_ctr[2];                          // tile counters

// ===========================================================================
// helpers
// ===========================================================================
__device__ __forceinline__ unsigned smem_u32(const void* p) {
    unsigned a;
    asm("{ .reg .u64 t; cvta.to.shared.u64 t, %1; cvt.u32.u64 %0, t; }"
        : "=r"(a) : "l"(p));
    return a;
}
__device__ __forceinline__ void ldsm4(unsigned* r, unsigned addr) {
    asm volatile("ldmatrix.sync.aligned.m8n8.x4.shared.b16 {%0,%1,%2,%3}, [%4];"
                 : "=r"(r[0]), "=r"(r[1]), "=r"(r[2]), "=r"(r[3]) : "r"(addr));
}
__device__ __forceinline__ void ldsm4t(unsigned* r, unsigned addr) {
    asm volatile("ldmatrix.sync.aligned.m8n8.x4.trans.shared.b16 {%0,%1,%2,%3}, [%4];"
                 : "=r"(r[0]), "=r"(r[1]), "=r"(r[2]), "=r"(r[3]) : "r"(addr));
}
__device__ __forceinline__ void mma16816(float* c, const unsigned* a,
                                         const unsigned* b) {
    asm volatile(
        "mma.sync.aligned.m16n8k16.row.col.f32.bf16.bf16.f32 "
        "{%0,%1,%2,%3}, {%4,%5,%6,%7}, {%8,%9}, {%0,%1,%2,%3};"
        : "+f"(c[0]), "+f"(c[1]), "+f"(c[2]), "+f"(c[3])
        : "r"(a[0]), "r"(a[1]), "r"(a[2]), "r"(a[3]), "r"(b[0]), "r"(b[1]));
}
__device__ __forceinline__ unsigned pack_bf16(bf16 x, bf16 y) {
    return ((unsigned)__bfloat16_as_ushort(y) << 16) | __bfloat16_as_ushort(x);
}
#define CP_ASYNC16(dst, src) \
    asm volatile("cp.async.cg.shared.global [%0], [%1], 16;" :: "r"(dst), "l"(src))
#define CP_COMMIT() asm volatile("cp.async.commit_group;" ::: "memory")
#define CP_WAIT0()  asm volatile("cp.async.wait_group 0;" ::: "memory")
#define CP_WAIT1()  asm volatile("cp.async.wait_group 1;" ::: "memory")

// ===========================================================================
// Fused split kernel: x + 4 weights in one launch; also resets tile counters.
// Block regions: [0,2048) -> x ; then 512 blocks per weight matrix.
// ===========================================================================
#define XBLK 2048            // (MROWS*HIDN/8)/256
#define WBLK 512             // (HIDN*HIDN/8)/256

__global__ void split_all(const float* __restrict__ x,
                          const float* __restrict__ Wq,
                          const float* __restrict__ Wk,
                          const float* __restrict__ Wv,
                          const float* __restrict__ Wo,
                          bf16* __restrict__ xh, bf16* __restrict__ xl,
                          bf16* __restrict__ w8)
{
    if (blockIdx.x == 0 && threadIdx.x == 0) { g_ctr[0] = 0; g_ctr[1] = 0; }

    const float* src;
    bf16 *hi, *lo;
    int lb;
    const int W2 = HIDN * HIDN;
    if (blockIdx.x < XBLK) {
        src = x; hi = xh; lo = xl; lb = blockIdx.x;
    } else {
        const int wi = (blockIdx.x - XBLK) / WBLK;        // 0..3
        lb = (blockIdx.x - XBLK) % WBLK;
        src = (wi == 0) ? Wq : (wi == 1) ? Wk : (wi == 2) ? Wv : Wo;
        hi = w8 + (size_t)(2 * wi) * W2;
        lo = w8 + (size_t)(2 * wi + 1) * W2;
    }

    const int base = (lb * 256 + threadIdx.x) * 2;
    float4 va = ((const float4*)src)[base];
    float4 vb = ((const float4*)src)[base + 1];
#pragma unroll
    for (int u = 0; u < 2; u++) {
        const float4 v = u ? vb : va;
        const int i = base + u;
        bf16 h0 = __float2bfloat16_rn(v.x);
        bf16 h1 = __float2bfloat16_rn(v.y);
        bf16 h2 = __float2bfloat16_rn(v.z);
        bf16 h3 = __float2bfloat16_rn(v.w);
        uint2 ho, lo2;
        ho.x = pack_bf16(h0, h1); ho.y = pack_bf16(h2, h3);
        lo2.x = pack_bf16(__float2bfloat16_rn(v.x - __bfloat162float(h0)),
                          __float2bfloat16_rn(v.y - __bfloat162float(h1)));
        lo2.y = pack_bf16(__float2bfloat16_rn(v.z - __bfloat162float(h2)),
                          __float2bfloat16_rn(v.w - __bfloat162float(h3)));
        ((uint2*)hi)[i] = ho;
        ((uint2*)lo)[i] = lo2;
    }
}

// ===========================================================================
// Persistent GEMM (unchanged from R12): tiles from global atomic counter.
// ===========================================================================
struct Job {
    const bf16* Wh; const bf16* Wl;
    const float* bias;
    bf16* Oh; bf16* Ol;
    float* Cf;
    float scl;
};

#define GST       40
#define GTILE_B   (128 * GST * 2)        // 10240 B per component tile
#define GSTAGE_B  (4 * GTILE_B)          // 40960 B
#define GSM_BYTES (2 * GSTAGE_B + 128)   // 82048 B
#define NCH2      (HIDN / 32)            // 32 chunks

__global__ __launch_bounds__(256, 2)
void gemm_pers(unsigned* ctr, int ntot,
               const bf16* __restrict__ Ah, const bf16* __restrict__ Al,
               Job j0, Job j1, Job j2)
{
    extern __shared__ char sm[];
    volatile int* slot = (volatile int*)(sm + 2 * GSTAGE_B);
    const int tid  = threadIdx.x;
    const int lane = tid & 31;
    const int wid  = tid >> 5;
    const int wm   = wid >> 2;           // 0..1
    const int wn   = wid & 3;            // 0..3

    const bf16* gsrc[4];

    auto setsrc = [&](int tile) {
        const int m  = tile >> 8;
        const int tt = tile & 255;
        const int bm = tt >> 3, bn = tt & 7;
        const Job& jb = (m == 0) ? j0 : (m == 1 ? j1 : j2);
        gsrc[0] = Ah + (size_t)bm * 128 * HIDN;
        gsrc[1] = Al + (size_t)bm * 128 * HIDN;
        gsrc[2] = jb.Wh + (size_t)bn * 128 * HIDN;
        gsrc[3] = jb.Wl + (size_t)bn * 128 * HIDN;
    };

    auto issue = [&](int kt, int buf) {
        char* st = sm + buf * GSTAGE_B;
#pragma unroll
        for (int t4 = 0; t4 < 4; t4++) {
#pragma unroll
            for (int j = 0; j < 2; j++) {
                const int ch = tid + j * 256;       // 0..511
                const int row = ch >> 2, cc = ch & 3;
                unsigned dst = smem_u32(st + t4 * GTILE_B + (row * GST + cc * 8) * 2);
                const bf16* src = gsrc[t4] + (size_t)row * HIDN + kt + cc * 8;
                CP_ASYNC16(dst, src);
            }
        }
        CP_COMMIT();
    };

    if (tid == 0) *slot = (int)atomicAdd(ctr, 1u);
    __syncthreads();
    int t = *slot;
    if (t >= ntot) return;
    setsrc(t);
    issue(0, 0);

    const int fr = lane & 15;
    const int fc = (lane >> 4) << 3;
    const int g = lane >> 2, tq = lane & 3;

    while (true) {
        float acc[4][4][4];
#pragma unroll
        for (int i = 0; i < 4; i++)
#pragma unroll
            for (int j = 0; j < 4; j++)
#pragma unroll
                for (int k = 0; k < 4; k++) acc[i][j][k] = 0.f;

        int tn = ntot;
        for (int c = 0; c < NCH2; c++) {
            CP_WAIT0();
            __syncthreads();
            if (c == NCH2 - 2 && tid == 0) *slot = (int)atomicAdd(ctr, 1u);
            if (c < NCH2 - 1) {
                issue((c + 1) * 32, (c + 1) & 1);
            } else {
                tn = *slot;
                if (tn < ntot) { setsrc(tn); issue(0, 0); }
            }

            const unsigned sb = smem_u32(sm) + (c & 1) * GSTAGE_B;
            const unsigned uAh = sb, uAl = sb + GTILE_B;
            const unsigned uWh = sb + 2 * GTILE_B, uWl = sb + 3 * GTILE_B;

#pragma unroll
            for (int ks = 0; ks < 2; ks++) {
                const int kcol = ks * 16 + fc;
                unsigned ah[4][4], al[4][4], bh[4][2], bl[4][2];
#pragma unroll
                for (int mt = 0; mt < 4; mt++) {
                    const unsigned off = ((wm * 64 + mt * 16 + fr) * GST + kcol) * 2;
                    ldsm4(ah[mt], uAh + off);
                    ldsm4(al[mt], uAl + off);
                }
#pragma unroll
                for (int ntp = 0; ntp < 2; ntp++) {
                    const unsigned off = ((wn * 32 + ntp * 16 + fr) * GST + kcol) * 2;
                    unsigned r[4];
                    ldsm4(r, uWh + off);
                    bh[2*ntp][0] = r[0]; bh[2*ntp+1][0] = r[1];
                    bh[2*ntp][1] = r[2]; bh[2*ntp+1][1] = r[3];
                    ldsm4(r, uWl + off);
                    bl[2*ntp][0] = r[0]; bl[2*ntp+1][0] = r[1];
                    bl[2*ntp][1] = r[2]; bl[2*ntp+1][1] = r[3];
                }
#pragma unroll
                for (int mt = 0; mt < 4; mt++)
#pragma unroll
                    for (int nt = 0; nt < 4; nt++) {
                        mma16816(acc[mt][nt], ah[mt], bh[nt]);
                        mma16816(acc[mt][nt], ah[mt], bl[nt]);
                        mma16816(acc[mt][nt], al[mt], bh[nt]);
                    }
            }
        }

        {
            const int m  = t >> 8;
            const int tt = t & 255;
            const int bm = tt >> 3, bn = tt & 7;
            const Job& jb = (m == 0) ? j0 : (m == 1 ? j1 : j2);
#pragma unroll
            for (int mt = 0; mt < 4; mt++) {
#pragma unroll
                for (int nt = 0; nt < 4; nt++) {
                    const int n = bn * 128 + wn * 32 + nt * 8 + 2 * tq;
                    const float2 bi = *(const float2*)(jb.bias + n);
                    const int m0 = bm * 128 + wm * 64 + mt * 16 + g;
#pragma unroll
                    for (int half = 0; half < 2; half++) {
                        const int mr = m0 + half * 8;
                        float vx = (acc[mt][nt][half * 2 + 0] + bi.x) * jb.scl;
                        float vy = (acc[mt][nt][half * 2 + 1] + bi.y) * jb.scl;
                        if (jb.Cf) {
                            *(float2*)(jb.Cf + (size_t)mr * HIDN + n) =
                                make_float2(vx, vy);
                        } else {
                            const int b = mr >> 11, s = mr & 2047;
                            const int hh = n >> 6, d = n & 63;
                            const size_t idx =
                                (((size_t)(b * HEADS + hh)) * SEQ + s) * HD + d;
                            bf16 h0 = __float2bfloat16_rn(vx);
                            bf16 h1 = __float2bfloat16_rn(vy);
                            *(unsigned*)(jb.Oh + idx) = pack_bf16(h0, h1);
                            *(unsigned*)(jb.Ol + idx) = pack_bf16(
                                __float2bfloat16_rn(vx - __bfloat162float(h0)),
                                __float2bfloat16_rn(vy - __bfloat162float(h1)));
                        }
                    }
                }
            }
        }

        if (tn >= ntot) return;
        t = tn;
    }
}

// ===========================================================================
// Block-causal flash attention: split K/V cp.async commit groups so S-MMA
// waits only on K; V completes under the softmax exchange sync.
// ===========================================================================
#define AST     72
#define ATILE_B (64 * AST * 2)            // 9216 B
#define AOFF_STAGE 18432
#define AOFF_XM  (AOFF_STAGE + 2 * 4 * ATILE_B)   // 92160
#define ATTN_SMEM (AOFF_XM + 2048)        // 94208 B

__global__ __launch_bounds__(256, 2)
void attn_mma2(const bf16* __restrict__ gqh, const bf16* __restrict__ gql,
               const bf16* __restrict__ gkh, const bf16* __restrict__ gkl,
               const bf16* __restrict__ gvh, const bf16* __restrict__ gvl,
               bf16* __restrict__ goh, bf16* __restrict__ gol)
{
    extern __shared__ char sm[];
    const int qb = NQB - 1 - blockIdx.x;
    const int h = blockIdx.y, b = blockIdx.z;
    const int tid  = threadIdx.x;
    const int lane = tid & 31;
    const int wid  = tid >> 5;
    const int wm   = wid >> 1;
    const int wn   = wid & 1;
    const int fr = lane & 15, fc = (lane >> 4) << 3;
    const int g  = lane >> 2, t = lane & 3;
    const int vkr = ((lane >> 4) << 3) + (lane & 7);
    const int vnc = ((lane >> 3) & 1) << 3;

    const size_t hb = ((size_t)(b * HEADS + h)) * SEQ * HD;
    const bf16* src_k[4];
    src_k[0] = gkh + hb; src_k[1] = gkl + hb;
    src_k[2] = gvh + hb; src_k[3] = gvl + hb;

    // K tiles = slots 0,1 of the stage; V tiles = slots 2,3. Separate groups.
    auto issueK = [&](int kb) {
        char* st = sm + AOFF_STAGE + (kb & 1) * 4 * ATILE_B;
        const size_t koff = (size_t)kb * 64 * HD;
#pragma unroll
        for (int t4 = 0; t4 < 2; t4++) {
#pragma unroll
            for (int j = 0; j < 2; j++) {
                const int ch = tid + j * 256;
                const int row = ch >> 3, cc = ch & 7;
                unsigned dst = smem_u32(st + t4 * ATILE_B + (row * AST + cc * 8) * 2);
                CP_ASYNC16(dst, src_k[t4] + koff + row * HD + cc * 8);
            }
        }
        CP_COMMIT();
    };
    auto issueV = [&](int kb) {
        char* st = sm + AOFF_STAGE + (kb & 1) * 4 * ATILE_B;
        const size_t koff = (size_t)kb * 64 * HD;
#pragma unroll
        for (int t4 = 2; t4 < 4; t4++) {
#pragma unroll
            for (int j = 0; j < 2; j++) {
                const int ch = tid + j * 256;
                const int row = ch >> 3, cc = ch & 7;
                unsigned dst = smem_u32(st + t4 * ATILE_B + (row * AST + cc * 8) * 2);
                CP_ASYNC16(dst, src_k[t4] + koff + row * HD + cc * 8);
            }
        }
        CP_COMMIT();
    };

    issueK(0);
    issueV(0);

    {
        const bf16* qh = gqh + hb + (size_t)qb * 64 * HD;
        const bf16* ql = gql + hb + (size_t)qb * 64 * HD;
#pragma unroll
        for (int j = 0; j < 2; j++) {
            const int ch = tid + j * 256;
            const int row = ch >> 3, cc = ch & 7;
            *(uint4*)(sm + (row * AST + cc * 8) * 2) =
                *(const uint4*)(qh + row * HD + cc * 8);
            *(uint4*)(sm + ATILE_B + (row * AST + cc * 8) * 2) =
                *(const uint4*)(ql + row * HD + cc * 8);
        }
    }

    const unsigned uQh = smem_u32(sm), uQl = uQh + ATILE_B;

    float o_acc[8][4];
#pragma unroll
    for (int i = 0; i < 8; i++)
#pragma unroll
        for (int j = 0; j < 4; j++) o_acc[i][j] = 0.f;
    float m0r = -1e30f, m1r = -1e30f, l0r = 0.f, l1r = 0.f;

    for (int kb = 0; kb <= qb; kb++) {
        // K_kb resident (V_kb may still be in flight: groups retire in order)
        CP_WAIT1();
        __syncthreads();
        if (kb + 1 <= qb) issueK(kb + 1);

        float* xm = (float*)(sm + AOFF_XM + (kb & 1) * 512);
        float* xl = (float*)(sm + AOFF_XM + 1024 + (kb & 1) * 512);

        const unsigned us = smem_u32(sm) + AOFF_STAGE + (kb & 1) * 4 * ATILE_B;
        const unsigned uKh = us, uKl = us + ATILE_B;
        const unsigned uVh = us + 2 * ATILE_B, uVl = us + 3 * ATILE_B;

        float sfr[4][4];
#pragma unroll
        for (int i = 0; i < 4; i++)
#pragma unroll
            for (int j = 0; j < 4; j++) sfr[i][j] = 0.f;

#pragma unroll
        for (int ks = 0; ks < 4; ks++) {
            const int kcol = ks * 16 + fc;
            unsigned qa_h[4], qa_l[4];
            const unsigned offa = ((wm * 16 + fr) * AST + kcol) * 2;
            ldsm4(qa_h, uQh + offa);
            ldsm4(qa_l, uQl + offa);
#pragma unroll
            for (int ntp = 0; ntp < 2; ntp++) {
                const unsigned offb = ((wn * 32 + ntp * 16 + fr) * AST + kcol) * 2;
                unsigned rh[4], rl[4];
                ldsm4(rh, uKh + offb);
                ldsm4(rl, uKl + offb);
                unsigned bh0[2] = {rh[0], rh[2]}, bh1[2] = {rh[1], rh[3]};
                unsigned bl0[2] = {rl[0], rl[2]}, bl1[2] = {rl[1], rl[3]};
                mma16816(sfr[2*ntp],   qa_h, bh0);
                mma16816(sfr[2*ntp],   qa_h, bl0);
                mma16816(sfr[2*ntp],   qa_l, bh0);
                mma16816(sfr[2*ntp+1], qa_h, bh1);
                mma16816(sfr[2*ntp+1], qa_h, bl1);
                mma16816(sfr[2*ntp+1], qa_l, bh1);
            }
        }

        // register softmax (local max/sum over this warp's k-half)
        float pm0 = sfr[0][0], pm1 = sfr[0][2];
#pragma unroll
        for (int nt = 0; nt < 4; nt++) {
            pm0 = fmaxf(pm0, fmaxf(sfr[nt][0], sfr[nt][1]));
            pm1 = fmaxf(pm1, fmaxf(sfr[nt][2], sfr[nt][3]));
        }
        pm0 = fmaxf(pm0, __shfl_xor_sync(0xffffffffu, pm0, 1));
        pm0 = fmaxf(pm0, __shfl_xor_sync(0xffffffffu, pm0, 2));
        pm1 = fmaxf(pm1, __shfl_xor_sync(0xffffffffu, pm1, 1));
        pm1 = fmaxf(pm1, __shfl_xor_sync(0xffffffffu, pm1, 2));

        float ps0 = 0.f, ps1 = 0.f;
#pragma unroll
        for (int nt = 0; nt < 4; nt++) {
            sfr[nt][0] = __expf(sfr[nt][0] - pm0);
            sfr[nt][1] = __expf(sfr[nt][1] - pm0);
            sfr[nt][2] = __expf(sfr[nt][2] - pm1);
            sfr[nt][3] = __expf(sfr[nt][3] - pm1);
            ps0 += sfr[nt][0] + sfr[nt][1];
            ps1 += sfr[nt][2] + sfr[nt][3];
        }
        ps0 += __shfl_xor_sync(0xffffffffu, ps0, 1);
        ps0 += __shfl_xor_sync(0xffffffffu, ps0, 2);
        ps1 += __shfl_xor_sync(0xffffffffu, ps1, 1);
        ps1 += __shfl_xor_sync(0xffffffffu, ps1, 2);

        if (t == 0) {
            xm[wn * 64 + wm * 16 + g]     = pm0;
            xm[wn * 64 + wm * 16 + g + 8] = pm1;
            xl[wn * 64 + wm * 16 + g]     = ps0;
            xl[wn * 64 + wm * 16 + g + 8] = ps1;
        }
        // V_kb resident after this (pending: K_{kb+1})
        CP_WAIT1();
        __syncthreads();
        if (kb + 1 <= qb) issueV(kb + 1);

        const int r0 = wm * 16 + g;
        const float ma0 = xm[r0],    mb0 = xm[64 + r0];
        const float la0 = xl[r0],    lb0 = xl[64 + r0];
        const float ma1 = xm[r0+8],  mb1 = xm[64 + r0 + 8];
        const float la1 = xl[r0+8],  lb1 = xl[64 + r0 + 8];
        const float mt0 = fmaxf(ma0, mb0), mt1 = fmaxf(ma1, mb1);
        const float lt0 = la0 * __expf(ma0 - mt0) + lb0 * __expf(mb0 - mt0);
        const float lt1 = la1 * __expf(ma1 - mt1) + lb1 * __expf(mb1 - mt1);

        const float mnew0 = fmaxf(m0r, mt0), mnew1 = fmaxf(m1r, mt1);
        const float corr0 = __expf(m0r - mnew0), corr1 = __expf(m1r - mnew1);
        l0r = l0r * corr0 + lt0 * __expf(mt0 - mnew0);
        l1r = l1r * corr1 + lt1 * __expf(mt1 - mnew1);
        m0r = mnew0; m1r = mnew1;

        const float pf0 = __expf(pm0 - mnew0), pf1 = __expf(pm1 - mnew1);
#pragma unroll
        for (int nt = 0; nt < 4; nt++) {
            sfr[nt][0] *= pf0; sfr[nt][1] *= pf0;
            sfr[nt][2] *= pf1; sfr[nt][3] *= pf1;
        }
#pragma unroll
        for (int n8 = 0; n8 < 8; n8++) {
            o_acc[n8][0] *= corr0; o_acc[n8][1] *= corr0;
            o_acc[n8][2] *= corr1; o_acc[n8][3] *= corr1;
        }

        // P -> A fragments (bf16 hi/lo) in registers
        unsigned pa_h[2][4], pa_l[2][4];
#pragma unroll
        for (int ks2 = 0; ks2 < 2; ks2++) {
            const int ntA = 2 * ks2, ntB = 2 * ks2 + 1;
            const float p00 = sfr[ntA][0], p01 = sfr[ntA][1];
            const float p02 = sfr[ntA][2], p03 = sfr[ntA][3];
            const float p10 = sfr[ntB][0], p11 = sfr[ntB][1];
            const float p12 = sfr[ntB][2], p13 = sfr[ntB][3];
            const bf16 h00 = __float2bfloat16_rn(p00), h01 = __float2bfloat16_rn(p01);
            const bf16 h02 = __float2bfloat16_rn(p02), h03 = __float2bfloat16_rn(p03);
            const bf16 h10 = __float2bfloat16_rn(p10), h11 = __float2bfloat16_rn(p11);
            const bf16 h12 = __float2bfloat16_rn(p12), h13 = __float2bfloat16_rn(p13);
            pa_h[ks2][0] = pack_bf16(h00, h01);
            pa_h[ks2][1] = pack_bf16(h02, h03);
            pa_h[ks2][2] = pack_bf16(h10, h11);
            pa_h[ks2][3] = pack_bf16(h12, h13);
            pa_l[ks2][0] = pack_bf16(
                __float2bfloat16_rn(p00 - __bfloat162float(h00)),
                __float2bfloat16_rn(p01 - __bfloat162float(h01)));
            pa_l[ks2][1] = pack_bf16(
                __float2bfloat16_rn(p02 - __bfloat162float(h02)),
                __float2bfloat16_rn(p03 - __bfloat162float(h03)));
            pa_l[ks2][2] = pack_bf16(
                __float2bfloat16_rn(p10 - __bfloat162float(h10)),
                __float2bfloat16_rn(p11 - __bfloat162float(h11)));
            pa_l[ks2][3] = pack_bf16(
                __float2bfloat16_rn(p12 - __bfloat162float(h12)),
                __float2bfloat16_rn(p13 - __bfloat162float(h13)));
        }

        // O += P V (this warp's k-half)
#pragma unroll
        for (int ks2 = 0; ks2 < 2; ks2++) {
#pragma unroll
            for (int nc = 0; nc < 4; nc++) {
                const unsigned offv =
                    ((wn * 32 + ks2 * 16 + vkr) * AST + nc * 16 + vnc) * 2;
                unsigned rh[4], rl[4];
                ldsm4t(rh, uVh + offv);
                ldsm4t(rl, uVl + offv);
                unsigned bh0[2] = {rh[0], rh[2]}, bh1[2] = {rh[1], rh[3]};
                unsigned bl0[2] = {rl[0], rl[2]}, bl1[2] = {rl[1], rl[3]};
                mma16816(o_acc[nc*2],   pa_h[ks2], bh0);
                mma16816(o_acc[nc*2],   pa_h[ks2], bl0);
                mma16816(o_acc[nc*2],   pa_l[ks2], bh0);
                mma16816(o_acc[nc*2+1], pa_h[ks2], bh1);
                mma16816(o_acc[nc*2+1], pa_h[ks2], bl1);
                mma16816(o_acc[nc*2+1], pa_l[ks2], bh1);
            }
        }
        // no bottom sync: next top sync orders buffer reuse
    }
    __syncthreads();

    // cross-warp O reduction + split output
    float* red = (float*)(sm + AOFF_STAGE);     // [64][66]
    if (wn == 1) {
#pragma unroll
        for (int n8 = 0; n8 < 8; n8++) {
            const int col = n8 * 8 + 2 * t;
            red[(wm * 16 + g)     * 66 + col]     = o_acc[n8][0];
            red[(wm * 16 + g)     * 66 + col + 1] = o_acc[n8][1];
            red[(wm * 16 + g + 8) * 66 + col]     = o_acc[n8][2];
            red[(wm * 16 + g + 8) * 66 + col + 1] = o_acc[n8][3];
        }
    }
    __syncthreads();
    if (wn == 0) {
        const float inv0 = 1.f / l0r, inv1 = 1.f / l1r;
        const size_t obase = ((size_t)(b * SEQ + qb * 64)) * HIDN + h * HD;
#pragma unroll
        for (int n8 = 0; n8 < 8; n8++) {
            const int col = n8 * 8 + 2 * t;
            const float v0 = (o_acc[n8][0] + red[(wm*16+g)*66 + col])     * inv0;
            const float v1 = (o_acc[n8][1] + red[(wm*16+g)*66 + col + 1]) * inv0;
            const float v2 = (o_acc[n8][2] + red[(wm*16+g+8)*66 + col])     * inv1;
            const float v3 = (o_acc[n8][3] + red[(wm*16+g+8)*66 + col + 1]) * inv1;
            const bf16 h0 = __float2bfloat16_rn(v0), h1 = __float2bfloat16_rn(v1);
            const bf16 h2 = __float2bfloat16_rn(v2), h3 = __float2bfloat16_rn(v3);
            const size_t i0 = obase + (size_t)(wm * 16 + g) * HIDN + col;
            const size_t i1 = obase + (size_t)(wm * 16 + g + 8) * HIDN + col;
            *(unsigned*)(goh + i0) = pack_bf16(h0, h1);
            *(unsigned*)(gol + i0) = pack_bf16(
                __float2bfloat16_rn(v0 - __bfloat162float(h0)),
                __float2bfloat16_rn(v1 - __bfloat162float(h1)));
            *(unsigned*)(goh + i1) = pack_bf16(h2, h3);
            *(unsigned*)(gol + i1) = pack_bf16(
                __float2bfloat16_rn(v2 - __bfloat162float(h2)),
                __float2bfloat16_rn(v3 - __bfloat162float(h3)));
        }
    }
}

// ---------------------------------------------------------------------------
extern "C" void kernel_launch(void* const* d_in, const int* in_sizes, int n_in,
                              void* d_out, int out_size)
{
    const float* x  = (const float*)d_in[0];
    const float* Wq = (const float*)d_in[1];
    const float* bq = (const float*)d_in[2];
    const float* Wk = (const float*)d_in[3];
    const float* bk = (const float*)d_in[4];
    const float* Wv = (const float*)d_in[5];
    const float* bv = (const float*)d_in[6];
    const float* Wo = (const float*)d_in[7];
    const float* bo = (const float*)d_in[8];
    float* out = (float*)d_out;

    bf16 *xh, *xl, *w8, *qh, *ql, *kh, *kl, *vh, *vl, *ah, *al;
    unsigned* ctr;
    cudaGetSymbolAddress((void**)&xh, g_xh);
    cudaGetSymbolAddress((void**)&xl, g_xl);
    cudaGetSymbolAddress((void**)&w8, g_w8);
    cudaGetSymbolAddress((void**)&qh, g_qh);
    cudaGetSymbolAddress((void**)&ql, g_ql);
    cudaGetSymbolAddress((void**)&kh, g_kh);
    cudaGetSymbolAddress((void**)&kl, g_kl);
    cudaGetSymbolAddress((void**)&vh, g_vh);
    cudaGetSymbolAddress((void**)&vl, g_vl);
    cudaGetSymbolAddress((void**)&ah, g_ah);
    cudaGetSymbolAddress((void**)&al, g_al);
    cudaGetSymbolAddress((void**)&ctr, g_ctr);

    cudaFuncSetAttribute(gemm_pers,
                         cudaFuncAttributeMaxDynamicSharedMemorySize, GSM_BYTES);
    cudaFuncSetAttribute(attn_mma2,
                         cudaFuncAttributeMaxDynamicSharedMemorySize, ATTN_SMEM);

    const int W2 = HIDN * HIDN;

    // One fused launch: x + Wq/Wk/Wv/Wo splits + counter reset
    split_all<<<XBLK + 4 * WBLK, 256>>>(x, Wq, Wk, Wv, Wo, xh, xl, w8);

    Job jq = { w8 + 0*W2, w8 + 1*W2, bq, qh, ql, nullptr, 0.125f };
    Job jk = { w8 + 2*W2, w8 + 3*W2, bk, kh, kl, nullptr, 1.0f };
    Job jv = { w8 + 4*W2, w8 + 5*W2, bv, vh, vl, nullptr, 1.0f };
    Job jo = { w8 + 6*W2, w8 + 7*W2, bo, nullptr, nullptr, out, 1.0f };

    // Fused QKV: 768 tiles, dynamic stealing over 296 persistent CTAs
    gemm_pers<<<296, 256, GSM_BYTES>>>(ctr + 0, 768, xh, xl, jq, jk, jv);

    attn_mma2<<<dim3(NQB, HEADS, BSZ), 256, ATTN_SMEM>>>(qh, ql, kh, kl,
                                                         vh, vl, ah, al);

    // O projection: 256 tiles
    gemm_pers<<<296, 256, GSM_BYTES>>>(ctr + 1, 256, ah, al, jo, jo, jo);
}